// round 6
// baseline (speedup 1.0000x reference)
#include <cuda_runtime.h>
#include <cuda_bf16.h>

#define N_NODES  100000
#define N_EDGES  3200000
#define N_GRAPHS 512
#define HID      16
#define LABELS   10
#define PAD_LOG2 7
#define PAD      (1 << PAD_LOG2)     // max in-degree capacity (actual max ~70)

// ---------------- scratch (device globals; zero at load, self-cleaned) -------
__device__ int   g_cnt  [N_NODES];           // in-degree; zeroed by k_gather_final
__device__ int   g_pad  [(size_t)N_NODES * PAD];  // padded adjacency (src lists)
__device__ float g_hws_a[N_NODES * HID];     // layer-1 scaled features
__device__ float g_hws_b[N_NODES * HID];     // layer-2 scaled features
__device__ float g_gsum [N_GRAPHS * HID];    // zeroed by k_out
__device__ float g_gcnt [N_GRAPHS];          // zeroed by k_out

__device__ __forceinline__ void red_add_v4(float* addr, float4 v) {
    asm volatile("red.global.add.v4.f32 [%0], {%1,%2,%3,%4};"
                 :: "l"(addr), "f"(v.x), "f"(v.y), "f"(v.z), "f"(v.w)
                 : "memory");
}

// ---------------- K0: single-pass padded-adjacency build ---------------------
__global__ void k_fill(const int* __restrict__ src, const int* __restrict__ dst) {
    int t = blockIdx.x * blockDim.x + threadIdx.x;
    int e = t * 4;
    if (e + 3 < N_EDGES) {
        int4 s = __ldg((const int4*)(src + e));
        int4 d = __ldg((const int4*)(dst + e));
        int p0 = atomicAdd(&g_cnt[d.x], 1);
        int p1 = atomicAdd(&g_cnt[d.y], 1);
        int p2 = atomicAdd(&g_cnt[d.z], 1);
        int p3 = atomicAdd(&g_cnt[d.w], 1);
        if (p0 < PAD) g_pad[((size_t)d.x << PAD_LOG2) + p0] = s.x;
        if (p1 < PAD) g_pad[((size_t)d.y << PAD_LOG2) + p1] = s.y;
        if (p2 < PAD) g_pad[((size_t)d.z << PAD_LOG2) + p2] = s.z;
        if (p3 < PAD) g_pad[((size_t)d.w << PAD_LOG2) + p3] = s.w;
    } else {
        for (int k = e; k < N_EDGES; k++) {
            int d = __ldg(dst + k);
            int p = atomicAdd(&g_cnt[d], 1);
            if (p < PAD) g_pad[((size_t)d << PAD_LOG2) + p] = __ldg(src + k);
        }
    }
}

// ---------------- K1: embed, h0@W1, scale -> hws_a ---------------------------
__global__ void k_node1(const int* __restrict__ x, const float* __restrict__ emb,
                        const float* __restrict__ W1) {
    __shared__ float sW[HID * HID];
    if (threadIdx.x < HID * HID) sW[threadIdx.x] = W1[threadIdx.x];
    __syncthreads();
    int i = blockIdx.x * blockDim.x + threadIdx.x;
    if (i >= N_NODES) return;

    float dv = rsqrtf((float)(__ldg(&g_cnt[i]) + 1));   // +1 self loop

    int xi = x[i];
    float h0[HID];
    const float4* ep = (const float4*)(emb + (size_t)xi * HID);
#pragma unroll
    for (int q = 0; q < 4; q++) {
        float4 v = __ldg(ep + q);
        h0[4*q+0] = v.x; h0[4*q+1] = v.y; h0[4*q+2] = v.z; h0[4*q+3] = v.w;
    }
    float4* o = (float4*)(g_hws_a + (size_t)i * HID);
#pragma unroll
    for (int q = 0; q < 4; q++) {
        float4 r;
        float* rp = (float*)&r;
#pragma unroll
        for (int jj = 0; jj < 4; jj++) {
            int j = 4*q + jj;
            float s = 0.0f;
#pragma unroll
            for (int k = 0; k < HID; k++) s = fmaf(h0[k], sW[k*HID + j], s);
            rp[jj] = s * dv;
        }
        o[q] = r;
    }
}

// Shared gather core: returns this lane's quarter-sum (neighbors + self),
// identical value across the 8 lanes sharing a quarter.
__device__ __forceinline__ float4 gather_quarter(const float* hws, int node,
                                                 int lane, int q, int cnt) {
    const int* adj = g_pad + ((size_t)node << PAD_LOG2);
    float4 acc = make_float4(0.f, 0.f, 0.f, 0.f);
    for (int p = lane >> 2; p < cnt; p += 8) {
        int s = __ldg(adj + p);
        float4 v = __ldg((const float4*)(hws + (size_t)s * HID) + q);
        acc.x += v.x; acc.y += v.y; acc.z += v.z; acc.w += v.w;
    }
#pragma unroll
    for (int off = 4; off < 32; off <<= 1) {
        acc.x += __shfl_xor_sync(0xffffffffu, acc.x, off);
        acc.y += __shfl_xor_sync(0xffffffffu, acc.y, off);
        acc.z += __shfl_xor_sync(0xffffffffu, acc.z, off);
        acc.w += __shfl_xor_sync(0xffffffffu, acc.w, off);
    }
    float4 self = __ldg((const float4*)(hws + (size_t)node * HID) + q);
    acc.x += self.x; acc.y += self.y; acc.z += self.z; acc.w += self.w;
    return acc;
}

// ---------------- K2: gather(hws_a) + relu(dv*acc+b1) @ W2 * dv -> hws_b -----
__global__ void k_gather_mid(const float* __restrict__ W2,
                             const float* __restrict__ b1) {
    __shared__ float sW[HID * HID];
    __shared__ float sb[HID];
    if (threadIdx.x < HID * HID) sW[threadIdx.x] = W2[threadIdx.x];
    if (threadIdx.x < HID)       sb[threadIdx.x] = b1[threadIdx.x];
    __syncthreads();

    int node = (blockIdx.x * blockDim.x + threadIdx.x) >> 5;
    if (node >= N_NODES) return;
    int lane = threadIdx.x & 31;
    int q = lane & 3;
    int cnt = __ldg(&g_cnt[node]);
    if (cnt > PAD) cnt = PAD;
    float dv = rsqrtf((float)(cnt + 1));

    float4 acc = gather_quarter(g_hws_a, node, lane, q, cnt);

    // assemble full 16-vector h1 via intra-group shuffles (group = 4 lanes)
    int gbase = lane & ~3;
    float h1[HID];
#pragma unroll
    for (int j = 0; j < 4; j++) {
        float4 vj;
        vj.x = __shfl_sync(0xffffffffu, acc.x, gbase + j);
        vj.y = __shfl_sync(0xffffffffu, acc.y, gbase + j);
        vj.z = __shfl_sync(0xffffffffu, acc.z, gbase + j);
        vj.w = __shfl_sync(0xffffffffu, acc.w, gbase + j);
        h1[4*j+0] = fmaxf(fmaf(dv, vj.x, sb[4*j+0]), 0.0f);
        h1[4*j+1] = fmaxf(fmaf(dv, vj.y, sb[4*j+1]), 0.0f);
        h1[4*j+2] = fmaxf(fmaf(dv, vj.z, sb[4*j+2]), 0.0f);
        h1[4*j+3] = fmaxf(fmaf(dv, vj.w, sb[4*j+3]), 0.0f);
    }
    if (lane < 4) {                       // lane == q: compute my 4 GEMM outputs
        float4 r;
        float* rp = (float*)&r;
#pragma unroll
        for (int jj = 0; jj < 4; jj++) {
            int j = 4*q + jj;
            float s = 0.0f;
#pragma unroll
            for (int k = 0; k < HID; k++) s = fmaf(h1[k], sW[k*HID + j], s);
            rp[jj] = s * dv;
        }
        ((float4*)(g_hws_b + (size_t)node * HID))[q] = r;
    }
}

// ---------------- K3: gather(hws_b) + relu(dv*acc+b2) -> red into gsum -------
__global__ void k_gather_final(const int* __restrict__ batch,
                               const float* __restrict__ b2) {
    __shared__ float sb[HID];
    if (threadIdx.x < HID) sb[threadIdx.x] = b2[threadIdx.x];
    __syncthreads();

    int node = (blockIdx.x * blockDim.x + threadIdx.x) >> 5;
    if (node >= N_NODES) return;
    int lane = threadIdx.x & 31;
    int q = lane & 3;
    int cnt = __ldg(&g_cnt[node]);
    if (cnt > PAD) cnt = PAD;
    float dv = rsqrtf((float)(cnt + 1));

    float4 acc = gather_quarter(g_hws_b, node, lane, q, cnt);

    if (lane < 4) {                       // lane == q
        float4 h2;
        h2.x = fmaxf(fmaf(dv, acc.x, sb[4*q+0]), 0.0f);
        h2.y = fmaxf(fmaf(dv, acc.y, sb[4*q+1]), 0.0f);
        h2.z = fmaxf(fmaf(dv, acc.z, sb[4*q+2]), 0.0f);
        h2.w = fmaxf(fmaf(dv, acc.w, sb[4*q+3]), 0.0f);
        int b = __ldg(batch + node);
        red_add_v4(g_gsum + (size_t)b * HID + 4*q, h2);
        if (lane == 0) {
            atomicAdd(&g_gcnt[b], 1.0f);
            g_cnt[node] = 0;              // self-clean for next replay
        }
    }
}

// ---------------- K4: classifier head + self-clean of pool buffers -----------
__global__ void k_out(const float* __restrict__ Wc, const float* __restrict__ bc,
                      float* __restrict__ out) {
    __shared__ float sW[HID * LABELS];
    __shared__ float sb[LABELS];
    if (threadIdx.x < HID * LABELS) sW[threadIdx.x] = Wc[threadIdx.x];
    if (threadIdx.x < LABELS)       sb[threadIdx.x] = bc[threadIdx.x];
    __syncthreads();
    int g = blockIdx.x * blockDim.x + threadIdx.x;
    if (g >= N_GRAPHS) return;

    float inv = 1.0f / fmaxf(g_gcnt[g], 1.0f);
    float p[HID];
#pragma unroll
    for (int k = 0; k < HID; k++) p[k] = g_gsum[(size_t)g * HID + k] * inv;
#pragma unroll
    for (int l = 0; l < LABELS; l++) {
        float s = sb[l];
#pragma unroll
        for (int k = 0; k < HID; k++) s = fmaf(p[k], sW[k*LABELS + l], s);
        out[(size_t)g * LABELS + l] = s;
    }
    // self-clean for next replay
#pragma unroll
    for (int k = 0; k < HID; k++) g_gsum[(size_t)g * HID + k] = 0.0f;
    g_gcnt[g] = 0.0f;
}

// ---------------- launch ------------------------------------------------------
extern "C" void kernel_launch(void* const* d_in, const int* in_sizes, int n_in,
                              void* d_out, int out_size) {
    const int*   x     = (const int*)  d_in[0];
    const int*   ei    = (const int*)  d_in[1];
    const int*   batch = (const int*)  d_in[2];
    const float* emb   = (const float*)d_in[3];
    const float* W1    = (const float*)d_in[4];
    const float* b1    = (const float*)d_in[5];
    const float* W2    = (const float*)d_in[6];
    const float* b2    = (const float*)d_in[7];
    const float* Wc    = (const float*)d_in[8];
    const float* bc    = (const float*)d_in[9];
    float* out = (float*)d_out;

    const int* src = ei;             // edge_index[0]
    const int* dst = ei + N_EDGES;   // edge_index[1]

    const int TB = 256;
    int edge_t4 = (N_EDGES + 3) / 4;
    int gather_blocks = (N_NODES * 32 + TB - 1) / TB;

    k_fill        <<<(edge_t4 + TB - 1) / TB, TB>>>(src, dst);     // 0
    k_node1       <<<(N_NODES + TB - 1) / TB, TB>>>(x, emb, W1);   // 1
    k_gather_mid  <<<gather_blocks, TB>>>(W2, b1);                 // 2
    k_gather_final<<<gather_blocks, TB>>>(batch, b2);              // 3
    k_out         <<<(N_GRAPHS + TB - 1) / TB, TB>>>(Wc, bc, out); // 4
}

// round 7
// speedup vs baseline: 1.1417x; 1.1417x over previous
#include <cuda_runtime.h>
#include <cuda_bf16.h>

#define N_NODES  100000
#define N_EDGES  3200000
#define N_GRAPHS 512
#define HID      16
#define LABELS   10
#define POOL_CHUNK 8
#define PAD_LOG2 7
#define PAD      (1 << PAD_LOG2)     // max in-degree capacity (actual max ~70)

// ---------------- scratch (device globals; zero at load, self-cleaned) -------
__device__ int   g_cnt  [N_NODES];           // in-degree; zeroed by k_pool
__device__ int   g_pad  [(size_t)N_NODES * PAD];  // padded adjacency (src lists)
__device__ float g_hws_a[N_NODES * HID];     // layer-1 scaled features
__device__ float g_hws_b[N_NODES * HID];     // layer-2 scaled features
__device__ float g_acc  [N_NODES * HID];     // layer-2 aggregation result
__device__ float g_gsum [N_GRAPHS * HID];    // zeroed by k_out
__device__ float g_gcnt [N_GRAPHS];          // zeroed by k_out

__device__ __forceinline__ void red_add_v4(float* addr, float4 v) {
    asm volatile("red.global.add.v4.f32 [%0], {%1,%2,%3,%4};"
                 :: "l"(addr), "f"(v.x), "f"(v.y), "f"(v.z), "f"(v.w)
                 : "memory");
}

// ---------------- K0: single-pass padded-adjacency build ---------------------
__global__ void k_fill(const int* __restrict__ src, const int* __restrict__ dst) {
    int t = blockIdx.x * blockDim.x + threadIdx.x;
    int e = t * 4;
    if (e + 3 < N_EDGES) {
        int4 s = __ldg((const int4*)(src + e));
        int4 d = __ldg((const int4*)(dst + e));
        int p0 = atomicAdd(&g_cnt[d.x], 1);
        int p1 = atomicAdd(&g_cnt[d.y], 1);
        int p2 = atomicAdd(&g_cnt[d.z], 1);
        int p3 = atomicAdd(&g_cnt[d.w], 1);
        if (p0 < PAD) g_pad[((size_t)d.x << PAD_LOG2) + p0] = s.x;
        if (p1 < PAD) g_pad[((size_t)d.y << PAD_LOG2) + p1] = s.y;
        if (p2 < PAD) g_pad[((size_t)d.z << PAD_LOG2) + p2] = s.z;
        if (p3 < PAD) g_pad[((size_t)d.w << PAD_LOG2) + p3] = s.w;
    } else {
        for (int k = e; k < N_EDGES; k++) {
            int d = __ldg(dst + k);
            int p = atomicAdd(&g_cnt[d], 1);
            if (p < PAD) g_pad[((size_t)d << PAD_LOG2) + p] = __ldg(src + k);
        }
    }
}

// ---------------- K1: embed, h0@W1, scale -> hws_a ---------------------------
__global__ void k_node1(const int* __restrict__ x, const float* __restrict__ emb,
                        const float* __restrict__ W1) {
    __shared__ float sW[HID * HID];
    if (threadIdx.x < HID * HID) sW[threadIdx.x] = W1[threadIdx.x];
    __syncthreads();
    int i = blockIdx.x * blockDim.x + threadIdx.x;
    if (i >= N_NODES) return;

    float dv = rsqrtf((float)(__ldg(&g_cnt[i]) + 1));   // +1 self loop

    int xi = x[i];
    float h0[HID];
    const float4* ep = (const float4*)(emb + (size_t)xi * HID);
#pragma unroll
    for (int q = 0; q < 4; q++) {
        float4 v = __ldg(ep + q);
        h0[4*q+0] = v.x; h0[4*q+1] = v.y; h0[4*q+2] = v.z; h0[4*q+3] = v.w;
    }
    float4* o = (float4*)(g_hws_a + (size_t)i * HID);
#pragma unroll
    for (int q = 0; q < 4; q++) {
        float4 r;
        float* rp = (float*)&r;
#pragma unroll
        for (int jj = 0; jj < 4; jj++) {
            int j = 4*q + jj;
            float s = 0.0f;
#pragma unroll
            for (int k = 0; k < HID; k++) s = fmaf(h0[k], sW[k*HID + j], s);
            rp[jj] = s * dv;
        }
        o[q] = r;
    }
}

// Gather core (no self term): after the xor-reduce all lanes sharing a quarter
// hold that quarter's neighbor sum.
__device__ __forceinline__ float4 gather_quarter(const float* hws, int node,
                                                 int lane, int q, int cnt) {
    const int* adj = g_pad + ((size_t)node << PAD_LOG2);
    float4 acc = make_float4(0.f, 0.f, 0.f, 0.f);
    for (int p = lane >> 2; p < cnt; p += 8) {
        int s = __ldg(adj + p);
        float4 v = __ldg((const float4*)(hws + (size_t)s * HID) + q);
        acc.x += v.x; acc.y += v.y; acc.z += v.z; acc.w += v.w;
    }
#pragma unroll
    for (int off = 4; off < 32; off <<= 1) {
        acc.x += __shfl_xor_sync(0xffffffffu, acc.x, off);
        acc.y += __shfl_xor_sync(0xffffffffu, acc.y, off);
        acc.z += __shfl_xor_sync(0xffffffffu, acc.z, off);
        acc.w += __shfl_xor_sync(0xffffffffu, acc.w, off);
    }
    return acc;
}

// ---------------- K2: gather(hws_a)+self, relu(dv*acc+b1) @ W2 * dv -> hws_b -
__global__ void k_gather_mid(const float* __restrict__ W2,
                             const float* __restrict__ b1) {
    __shared__ float sW[HID * HID];
    __shared__ float sb[HID];
    if (threadIdx.x < HID * HID) sW[threadIdx.x] = W2[threadIdx.x];
    if (threadIdx.x < HID)       sb[threadIdx.x] = b1[threadIdx.x];
    __syncthreads();

    int node = (blockIdx.x * blockDim.x + threadIdx.x) >> 5;
    if (node >= N_NODES) return;
    int lane = threadIdx.x & 31;
    int q = lane & 3;
    int cnt = __ldg(&g_cnt[node]);
    if (cnt > PAD) cnt = PAD;
    float dv = rsqrtf((float)(cnt + 1));

    float4 acc = gather_quarter(g_hws_a, node, lane, q, cnt);
    // add self term (all lanes; broadcast load)
    {
        float4 self = __ldg((const float4*)(g_hws_a + (size_t)node * HID) + q);
        acc.x += self.x; acc.y += self.y; acc.z += self.z; acc.w += self.w;
    }

    // assemble full 16-vector h1 via intra-group shuffles (group = 4 lanes)
    int gbase = lane & ~3;
    float h1[HID];
#pragma unroll
    for (int j = 0; j < 4; j++) {
        float4 vj;
        vj.x = __shfl_sync(0xffffffffu, acc.x, gbase + j);
        vj.y = __shfl_sync(0xffffffffu, acc.y, gbase + j);
        vj.z = __shfl_sync(0xffffffffu, acc.z, gbase + j);
        vj.w = __shfl_sync(0xffffffffu, acc.w, gbase + j);
        h1[4*j+0] = fmaxf(fmaf(dv, vj.x, sb[4*j+0]), 0.0f);
        h1[4*j+1] = fmaxf(fmaf(dv, vj.y, sb[4*j+1]), 0.0f);
        h1[4*j+2] = fmaxf(fmaf(dv, vj.z, sb[4*j+2]), 0.0f);
        h1[4*j+3] = fmaxf(fmaf(dv, vj.w, sb[4*j+3]), 0.0f);
    }
    if (lane < 4) {                       // lane == q: compute my 4 GEMM outputs
        float4 r;
        float* rp = (float*)&r;
#pragma unroll
        for (int jj = 0; jj < 4; jj++) {
            int j = 4*q + jj;
            float s = 0.0f;
#pragma unroll
            for (int k = 0; k < HID; k++) s = fmaf(h1[k], sW[k*HID + j], s);
            rp[jj] = s * dv;
        }
        ((float4*)(g_hws_b + (size_t)node * HID))[q] = r;
    }
}

// ---------------- K3: plain gather(hws_b)+self -> g_acc ----------------------
__global__ void k_gather2() {
    int node = (blockIdx.x * blockDim.x + threadIdx.x) >> 5;
    if (node >= N_NODES) return;
    int lane = threadIdx.x & 31;
    int q = lane & 3;
    int cnt = __ldg(&g_cnt[node]);
    if (cnt > PAD) cnt = PAD;

    float4 acc = gather_quarter(g_hws_b, node, lane, q, cnt);

    if (lane < 4) {                       // lane == q
        float4 self = __ldg((const float4*)(g_hws_b + (size_t)node * HID) + lane);
        acc.x += self.x; acc.y += self.y; acc.z += self.z; acc.w += self.w;
        ((float4*)(g_acc + (size_t)node * HID))[lane] = acc;
    }
}

// ---------------- K4: h2 = relu(dv*acc + b2); mean-pool (run-aggregated) -----
__global__ void k_pool(const int* __restrict__ batch, const float* __restrict__ b2) {
    int t = blockIdx.x * blockDim.x + threadIdx.x;
    int start = t * POOL_CHUNK;
    if (start >= N_NODES) return;
    int end = min(start + POOL_CHUNK, N_NODES);

    float sb[HID];
#pragma unroll
    for (int j = 0; j < HID; j++) sb[j] = __ldg(b2 + j);

    float lacc[HID];
#pragma unroll
    for (int j = 0; j < HID; j++) lacc[j] = 0.0f;
    float lcnt = 0.0f;
    int cur = __ldg(batch + start);

    for (int i = start; i < end; i++) {
        int bg = __ldg(batch + i);
        if (bg != cur) {
            float* gp = g_gsum + (size_t)cur * HID;
#pragma unroll
            for (int q = 0; q < 4; q++)
                red_add_v4(gp + 4*q, make_float4(lacc[4*q], lacc[4*q+1], lacc[4*q+2], lacc[4*q+3]));
            atomicAdd(&g_gcnt[cur], lcnt);
#pragma unroll
            for (int j = 0; j < HID; j++) lacc[j] = 0.0f;
            lcnt = 0.0f;
            cur = bg;
        }
        float dv = rsqrtf((float)(g_cnt[i] + 1));
        const float4* ap = (const float4*)(g_acc + (size_t)i * HID);
#pragma unroll
        for (int q = 0; q < 4; q++) {
            float4 v = ap[q];
            lacc[4*q+0] += fmaxf(fmaf(dv, v.x, sb[4*q+0]), 0.0f);
            lacc[4*q+1] += fmaxf(fmaf(dv, v.y, sb[4*q+1]), 0.0f);
            lacc[4*q+2] += fmaxf(fmaf(dv, v.z, sb[4*q+2]), 0.0f);
            lacc[4*q+3] += fmaxf(fmaf(dv, v.w, sb[4*q+3]), 0.0f);
        }
        lcnt += 1.0f;
        g_cnt[i] = 0;                          // self-clean for next replay
    }
    float* gp = g_gsum + (size_t)cur * HID;
#pragma unroll
    for (int q = 0; q < 4; q++)
        red_add_v4(gp + 4*q, make_float4(lacc[4*q], lacc[4*q+1], lacc[4*q+2], lacc[4*q+3]));
    atomicAdd(&g_gcnt[cur], lcnt);
}

// ---------------- K5: classifier head + self-clean of pool buffers -----------
__global__ void k_out(const float* __restrict__ Wc, const float* __restrict__ bc,
                      float* __restrict__ out) {
    __shared__ float sW[HID * LABELS];
    __shared__ float sb[LABELS];
    if (threadIdx.x < HID * LABELS) sW[threadIdx.x] = Wc[threadIdx.x];
    if (threadIdx.x < LABELS)       sb[threadIdx.x] = bc[threadIdx.x];
    __syncthreads();
    int g = blockIdx.x * blockDim.x + threadIdx.x;
    if (g >= N_GRAPHS) return;

    float inv = 1.0f / fmaxf(g_gcnt[g], 1.0f);
    float p[HID];
#pragma unroll
    for (int k = 0; k < HID; k++) p[k] = g_gsum[(size_t)g * HID + k] * inv;
#pragma unroll
    for (int l = 0; l < LABELS; l++) {
        float s = sb[l];
#pragma unroll
        for (int k = 0; k < HID; k++) s = fmaf(p[k], sW[k*LABELS + l], s);
        out[(size_t)g * LABELS + l] = s;
    }
    // self-clean for next replay
#pragma unroll
    for (int k = 0; k < HID; k++) g_gsum[(size_t)g * HID + k] = 0.0f;
    g_gcnt[g] = 0.0f;
}

// ---------------- launch ------------------------------------------------------
extern "C" void kernel_launch(void* const* d_in, const int* in_sizes, int n_in,
                              void* d_out, int out_size) {
    const int*   x     = (const int*)  d_in[0];
    const int*   ei    = (const int*)  d_in[1];
    const int*   batch = (const int*)  d_in[2];
    const float* emb   = (const float*)d_in[3];
    const float* W1    = (const float*)d_in[4];
    const float* b1    = (const float*)d_in[5];
    const float* W2    = (const float*)d_in[6];
    const float* b2    = (const float*)d_in[7];
    const float* Wc    = (const float*)d_in[8];
    const float* bc    = (const float*)d_in[9];
    float* out = (float*)d_out;

    const int* src = ei;             // edge_index[0]
    const int* dst = ei + N_EDGES;   // edge_index[1]

    const int TB = 256;
    int edge_t4 = (N_EDGES + 3) / 4;
    int gather_blocks = (N_NODES * 32 + TB - 1) / TB;
    int pool_threads = (N_NODES + POOL_CHUNK - 1) / POOL_CHUNK;

    k_fill      <<<(edge_t4 + TB - 1) / TB, TB>>>(src, dst);       // 0
    k_node1     <<<(N_NODES + TB - 1) / TB, TB>>>(x, emb, W1);     // 1
    k_gather_mid<<<gather_blocks, TB>>>(W2, b1);                   // 2
    k_gather2   <<<gather_blocks, TB>>>();                         // 3
    k_pool      <<<(pool_threads + TB - 1) / TB, TB>>>(batch, b2); // 4
    k_out       <<<(N_GRAPHS + TB - 1) / TB, TB>>>(Wc, bc, out);   // 5
}

// round 8
// speedup vs baseline: 1.1781x; 1.0318x over previous
#include <cuda_runtime.h>
#include <cuda_bf16.h>

#define N_NODES  100000
#define N_EDGES  3200000
#define N_GRAPHS 512
#define VOCAB    128
#define HID      16
#define LABELS   10
#define POOL_CHUNK 8
#define PAD_LOG2 7
#define PAD      (1 << PAD_LOG2)     // max in-degree capacity (actual max ~70)
#define T1S      20                  // padded T1 row stride in smem (bank spread)

// ---------------- scratch (device globals; zero at load, self-cleaned) -------
__device__ int   g_cnt  [N_NODES];           // in-degree; zeroed by k_pool
__device__ int   g_pad  [(size_t)N_NODES * PAD];  // padded adjacency (src lists)
__device__ float g_t1   [VOCAB * HID];       // T1 = emb @ W1
__device__ int2  g_combo[N_NODES];           // {x[i], bits(dinv[i])}
__device__ float g_hws_b[N_NODES * HID];     // layer-2 scaled features
__device__ float g_acc  [N_NODES * HID];     // aggregation result
__device__ float g_gsum [N_GRAPHS * HID];    // zeroed by k_out
__device__ float g_gcnt [N_GRAPHS];          // zeroed by k_out

__device__ __forceinline__ void red_add_v4(float* addr, float4 v) {
    asm volatile("red.global.add.v4.f32 [%0], {%1,%2,%3,%4};"
                 :: "l"(addr), "f"(v.x), "f"(v.y), "f"(v.z), "f"(v.w)
                 : "memory");
}

// ---------------- K0: single-pass padded-adjacency build ---------------------
__global__ void k_fill(const int* __restrict__ src, const int* __restrict__ dst) {
    int t = blockIdx.x * blockDim.x + threadIdx.x;
    int e = t * 4;
    if (e + 3 < N_EDGES) {
        int4 s = __ldg((const int4*)(src + e));
        int4 d = __ldg((const int4*)(dst + e));
        int p0 = atomicAdd(&g_cnt[d.x], 1);
        int p1 = atomicAdd(&g_cnt[d.y], 1);
        int p2 = atomicAdd(&g_cnt[d.z], 1);
        int p3 = atomicAdd(&g_cnt[d.w], 1);
        if (p0 < PAD) g_pad[((size_t)d.x << PAD_LOG2) + p0] = s.x;
        if (p1 < PAD) g_pad[((size_t)d.y << PAD_LOG2) + p1] = s.y;
        if (p2 < PAD) g_pad[((size_t)d.z << PAD_LOG2) + p2] = s.z;
        if (p3 < PAD) g_pad[((size_t)d.w << PAD_LOG2) + p3] = s.w;
    } else {
        for (int k = e; k < N_EDGES; k++) {
            int d = __ldg(dst + k);
            int p = atomicAdd(&g_cnt[d], 1);
            if (p < PAD) g_pad[((size_t)d << PAD_LOG2) + p] = __ldg(src + k);
        }
    }
}

// ---------------- K1: T1 = emb @ W1 (one block, 128 threads) -----------------
__global__ void k_t1(const float* __restrict__ emb, const float* __restrict__ W1) {
    __shared__ float sW[HID * HID];
    int t = threadIdx.x;                 // 0..127 = vocab row
    sW[t] = W1[t]; sW[t + 128] = W1[t + 128];
    __syncthreads();
    float e[HID];
    const float4* ep = (const float4*)(emb + (size_t)t * HID);
#pragma unroll
    for (int q = 0; q < 4; q++) {
        float4 v = __ldg(ep + q);
        e[4*q+0] = v.x; e[4*q+1] = v.y; e[4*q+2] = v.z; e[4*q+3] = v.w;
    }
#pragma unroll
    for (int j = 0; j < HID; j++) {
        float s = 0.0f;
#pragma unroll
        for (int k = 0; k < HID; k++) s = fmaf(e[k], sW[k*HID + j], s);
        g_t1[t * HID + j] = s;
    }
}

// ---------------- K2: combo[i] = {x[i], dinv[i]} -----------------------------
__global__ void k_combo(const int* __restrict__ x) {
    int i = blockIdx.x * blockDim.x + threadIdx.x;
    if (i >= N_NODES) return;
    float dv = rsqrtf((float)(__ldg(&g_cnt[i]) + 1));   // +1 self loop
    g_combo[i] = make_int2(__ldg(x + i), __float_as_int(dv));
}

// ---------------- K3: layer-1 gather via T1 table -> g_acc -------------------
// acc[i] = sum_{s in N(i)} dinv_s * T1[x_s]  +  dinv_i * T1[x_i]
__global__ void k_gather1() {
    __shared__ float sT1[VOCAB * T1S];
    for (int idx = threadIdx.x; idx < VOCAB * HID; idx += blockDim.x) {
        int v = idx >> 4, j = idx & 15;
        sT1[v * T1S + j] = g_t1[idx];
    }
    __syncthreads();

    int node = (blockIdx.x * blockDim.x + threadIdx.x) >> 5;
    if (node >= N_NODES) return;
    int lane = threadIdx.x & 31;
    int q = lane & 3;
    int cnt = __ldg(&g_cnt[node]);
    if (cnt > PAD) cnt = PAD;
    const int* adj = g_pad + ((size_t)node << PAD_LOG2);

    float4 acc = make_float4(0.f, 0.f, 0.f, 0.f);
    for (int p = lane >> 2; p < cnt; p += 8) {
        int s = __ldg(adj + p);
        int2 c = __ldg(&g_combo[s]);
        float dvs = __int_as_float(c.y);
        float4 tq = *(const float4*)(sT1 + c.x * T1S + q * 4);
        acc.x = fmaf(dvs, tq.x, acc.x);
        acc.y = fmaf(dvs, tq.y, acc.y);
        acc.z = fmaf(dvs, tq.z, acc.z);
        acc.w = fmaf(dvs, tq.w, acc.w);
    }
#pragma unroll
    for (int off = 4; off < 32; off <<= 1) {
        acc.x += __shfl_xor_sync(0xffffffffu, acc.x, off);
        acc.y += __shfl_xor_sync(0xffffffffu, acc.y, off);
        acc.z += __shfl_xor_sync(0xffffffffu, acc.z, off);
        acc.w += __shfl_xor_sync(0xffffffffu, acc.w, off);
    }
    if (lane < 4) {                       // lane == q: add self, store
        int2 c = __ldg(&g_combo[node]);
        float dvs = __int_as_float(c.y);
        float4 tq = *(const float4*)(sT1 + c.x * T1S + lane * 4);
        acc.x = fmaf(dvs, tq.x, acc.x);
        acc.y = fmaf(dvs, tq.y, acc.y);
        acc.z = fmaf(dvs, tq.z, acc.z);
        acc.w = fmaf(dvs, tq.w, acc.w);
        ((float4*)(g_acc + (size_t)node * HID))[lane] = acc;
    }
}

// ---------------- K4: h1 = relu(dv*acc + b1); h1@W2; scale -> hws_b ----------
__global__ void k_node2(const float* __restrict__ W2, const float* __restrict__ b1) {
    __shared__ float sW[HID * HID];
    __shared__ float sb[HID];
    if (threadIdx.x < HID * HID) sW[threadIdx.x] = W2[threadIdx.x];
    if (threadIdx.x < HID)       sb[threadIdx.x] = b1[threadIdx.x];
    __syncthreads();
    int i = blockIdx.x * blockDim.x + threadIdx.x;
    if (i >= N_NODES) return;

    float dv = __int_as_float(__ldg(&g_combo[i].y));
    float h1[HID];
    const float4* ap = (const float4*)(g_acc + (size_t)i * HID);
#pragma unroll
    for (int q = 0; q < 4; q++) {
        float4 v = ap[q];
        h1[4*q+0] = fmaxf(fmaf(dv, v.x, sb[4*q+0]), 0.0f);
        h1[4*q+1] = fmaxf(fmaf(dv, v.y, sb[4*q+1]), 0.0f);
        h1[4*q+2] = fmaxf(fmaf(dv, v.z, sb[4*q+2]), 0.0f);
        h1[4*q+3] = fmaxf(fmaf(dv, v.w, sb[4*q+3]), 0.0f);
    }
    float4* o = (float4*)(g_hws_b + (size_t)i * HID);
#pragma unroll
    for (int q = 0; q < 4; q++) {
        float4 r;
        float* rp = (float*)&r;
#pragma unroll
        for (int jj = 0; jj < 4; jj++) {
            int j = 4*q + jj;
            float s = 0.0f;
#pragma unroll
            for (int k = 0; k < HID; k++) s = fmaf(h1[k], sW[k*HID + j], s);
            rp[jj] = s * dv;
        }
        o[q] = r;
    }
}

// ---------------- K5: plain gather(hws_b)+self -> g_acc ----------------------
__global__ void k_gather2() {
    int node = (blockIdx.x * blockDim.x + threadIdx.x) >> 5;
    if (node >= N_NODES) return;
    int lane = threadIdx.x & 31;
    int q = lane & 3;
    int cnt = __ldg(&g_cnt[node]);
    if (cnt > PAD) cnt = PAD;
    const int* adj = g_pad + ((size_t)node << PAD_LOG2);

    float4 acc = make_float4(0.f, 0.f, 0.f, 0.f);
    for (int p = lane >> 2; p < cnt; p += 8) {
        int s = __ldg(adj + p);
        float4 v = __ldg((const float4*)(g_hws_b + (size_t)s * HID) + q);
        acc.x += v.x; acc.y += v.y; acc.z += v.z; acc.w += v.w;
    }
#pragma unroll
    for (int off = 4; off < 32; off <<= 1) {
        acc.x += __shfl_xor_sync(0xffffffffu, acc.x, off);
        acc.y += __shfl_xor_sync(0xffffffffu, acc.y, off);
        acc.z += __shfl_xor_sync(0xffffffffu, acc.z, off);
        acc.w += __shfl_xor_sync(0xffffffffu, acc.w, off);
    }
    if (lane < 4) {                       // lane == q
        float4 self = __ldg((const float4*)(g_hws_b + (size_t)node * HID) + lane);
        acc.x += self.x; acc.y += self.y; acc.z += self.z; acc.w += self.w;
        ((float4*)(g_acc + (size_t)node * HID))[lane] = acc;
    }
}

// ---------------- K6: h2 = relu(dv*acc + b2); mean-pool (run-aggregated) -----
__global__ void k_pool(const int* __restrict__ batch, const float* __restrict__ b2) {
    int t = blockIdx.x * blockDim.x + threadIdx.x;
    int start = t * POOL_CHUNK;
    if (start >= N_NODES) return;
    int end = min(start + POOL_CHUNK, N_NODES);

    float sb[HID];
#pragma unroll
    for (int j = 0; j < HID; j++) sb[j] = __ldg(b2 + j);

    float lacc[HID];
#pragma unroll
    for (int j = 0; j < HID; j++) lacc[j] = 0.0f;
    float lcnt = 0.0f;
    int cur = __ldg(batch + start);

    for (int i = start; i < end; i++) {
        int bg = __ldg(batch + i);
        if (bg != cur) {
            float* gp = g_gsum + (size_t)cur * HID;
#pragma unroll
            for (int q = 0; q < 4; q++)
                red_add_v4(gp + 4*q, make_float4(lacc[4*q], lacc[4*q+1], lacc[4*q+2], lacc[4*q+3]));
            atomicAdd(&g_gcnt[cur], lcnt);
#pragma unroll
            for (int j = 0; j < HID; j++) lacc[j] = 0.0f;
            lcnt = 0.0f;
            cur = bg;
        }
        float dv = __int_as_float(g_combo[i].y);
        const float4* ap = (const float4*)(g_acc + (size_t)i * HID);
#pragma unroll
        for (int q = 0; q < 4; q++) {
            float4 v = ap[q];
            lacc[4*q+0] += fmaxf(fmaf(dv, v.x, sb[4*q+0]), 0.0f);
            lacc[4*q+1] += fmaxf(fmaf(dv, v.y, sb[4*q+1]), 0.0f);
            lacc[4*q+2] += fmaxf(fmaf(dv, v.z, sb[4*q+2]), 0.0f);
            lacc[4*q+3] += fmaxf(fmaf(dv, v.w, sb[4*q+3]), 0.0f);
        }
        lcnt += 1.0f;
        g_cnt[i] = 0;                          // self-clean for next replay
    }
    float* gp = g_gsum + (size_t)cur * HID;
#pragma unroll
    for (int q = 0; q < 4; q++)
        red_add_v4(gp + 4*q, make_float4(lacc[4*q], lacc[4*q+1], lacc[4*q+2], lacc[4*q+3]));
    atomicAdd(&g_gcnt[cur], lcnt);
}

// ---------------- K7: classifier head + self-clean of pool buffers -----------
__global__ void k_out(const float* __restrict__ Wc, const float* __restrict__ bc,
                      float* __restrict__ out) {
    __shared__ float sW[HID * LABELS];
    __shared__ float sb[LABELS];
    if (threadIdx.x < HID * LABELS) sW[threadIdx.x] = Wc[threadIdx.x];
    if (threadIdx.x < LABELS)       sb[threadIdx.x] = bc[threadIdx.x];
    __syncthreads();
    int g = blockIdx.x * blockDim.x + threadIdx.x;
    if (g >= N_GRAPHS) return;

    float inv = 1.0f / fmaxf(g_gcnt[g], 1.0f);
    float p[HID];
#pragma unroll
    for (int k = 0; k < HID; k++) p[k] = g_gsum[(size_t)g * HID + k] * inv;
#pragma unroll
    for (int l = 0; l < LABELS; l++) {
        float s = sb[l];
#pragma unroll
        for (int k = 0; k < HID; k++) s = fmaf(p[k], sW[k*LABELS + l], s);
        out[(size_t)g * LABELS + l] = s;
    }
    // self-clean for next replay
#pragma unroll
    for (int k = 0; k < HID; k++) g_gsum[(size_t)g * HID + k] = 0.0f;
    g_gcnt[g] = 0.0f;
}

// ---------------- launch ------------------------------------------------------
extern "C" void kernel_launch(void* const* d_in, const int* in_sizes, int n_in,
                              void* d_out, int out_size) {
    const int*   x     = (const int*)  d_in[0];
    const int*   ei    = (const int*)  d_in[1];
    const int*   batch = (const int*)  d_in[2];
    const float* emb   = (const float*)d_in[3];
    const float* W1    = (const float*)d_in[4];
    const float* b1    = (const float*)d_in[5];
    const float* W2    = (const float*)d_in[6];
    const float* b2    = (const float*)d_in[7];
    const float* Wc    = (const float*)d_in[8];
    const float* bc    = (const float*)d_in[9];
    float* out = (float*)d_out;

    const int* src = ei;             // edge_index[0]
    const int* dst = ei + N_EDGES;   // edge_index[1]

    const int TB = 256;
    int edge_t4 = (N_EDGES + 3) / 4;
    int gather_blocks = (N_NODES * 32 + TB - 1) / TB;
    int pool_threads = (N_NODES + POOL_CHUNK - 1) / POOL_CHUNK;

    k_fill   <<<(edge_t4 + TB - 1) / TB, TB>>>(src, dst);       // 0
    k_t1     <<<1, 128>>>(emb, W1);                             // 1
    k_combo  <<<(N_NODES + TB - 1) / TB, TB>>>(x);              // 2
    k_gather1<<<gather_blocks, TB>>>();                         // 3
    k_node2  <<<(N_NODES + TB - 1) / TB, TB>>>(W2, b1);         // 4
    k_gather2<<<gather_blocks, TB>>>();                         // 5
    k_pool   <<<(pool_threads + TB - 1) / TB, TB>>>(batch, b2); // 6
    k_out    <<<(N_GRAPHS + TB - 1) / TB, TB>>>(Wc, bc, out);   // 7
}

// round 9
// speedup vs baseline: 1.3176x; 1.1184x over previous
#include <cuda_runtime.h>
#include <cuda_bf16.h>

#define N_NODES  100000
#define N_EDGES  3200000
#define N_GRAPHS 512
#define VOCAB    128
#define HID      16
#define LABELS   10
#define POOL_CHUNK 8
#define PAD_LOG2 7
#define PAD      (1 << PAD_LOG2)     // max in-degree capacity (actual max ~70)

// ---------------- scratch (device globals; zero at load, self-cleaned) -------
__device__ int   g_cnt [N_NODES];            // in-degree; zeroed by k_pool
__device__ int   g_pad [(size_t)N_NODES * PAD];  // padded adjacency (src lists)
__device__ float g_t1  [VOCAB * HID];        // T1 = emb @ W1
__device__ float g_hws [N_NODES * HID];      // scaled features (gather source)
__device__ float g_acc [N_NODES * HID];      // aggregation result
__device__ float g_gsum[N_GRAPHS * HID];     // zeroed by k_out
__device__ float g_gcnt[N_GRAPHS];           // zeroed by k_out

__device__ __forceinline__ void red_add_v4(float* addr, float4 v) {
    asm volatile("red.global.add.v4.f32 [%0], {%1,%2,%3,%4};"
                 :: "l"(addr), "f"(v.x), "f"(v.y), "f"(v.z), "f"(v.w)
                 : "memory");
}

// ---------------- K0: T1 = emb @ W1 (one block, 128 threads) -----------------
__global__ void k_t1(const float* __restrict__ emb, const float* __restrict__ W1) {
    __shared__ float sW[HID * HID];
    int t = threadIdx.x;                 // 0..127 = vocab row
    sW[t] = W1[t]; sW[t + 128] = W1[t + 128];
    __syncthreads();
    float e[HID];
    const float4* ep = (const float4*)(emb + (size_t)t * HID);
#pragma unroll
    for (int q = 0; q < 4; q++) {
        float4 v = __ldg(ep + q);
        e[4*q+0] = v.x; e[4*q+1] = v.y; e[4*q+2] = v.z; e[4*q+3] = v.w;
    }
#pragma unroll
    for (int j = 0; j < HID; j++) {
        float s = 0.0f;
#pragma unroll
        for (int k = 0; k < HID; k++) s = fmaf(e[k], sW[k*HID + j], s);
        g_t1[t * HID + j] = s;
    }
}

// ---------------- K1: single-pass padded-adjacency build (2 edges/thread) ----
__global__ void k_fill(const int* __restrict__ src, const int* __restrict__ dst) {
    int t = blockIdx.x * blockDim.x + threadIdx.x;
    int e = t * 2;
    if (e + 1 < N_EDGES) {
        int2 s = __ldg((const int2*)(src + e));
        int2 d = __ldg((const int2*)(dst + e));
        int p0 = atomicAdd(&g_cnt[d.x], 1);
        int p1 = atomicAdd(&g_cnt[d.y], 1);
        if (p0 < PAD) g_pad[((size_t)d.x << PAD_LOG2) + p0] = s.x;
        if (p1 < PAD) g_pad[((size_t)d.y << PAD_LOG2) + p1] = s.y;
    } else if (e < N_EDGES) {
        int d = __ldg(dst + e);
        int p = atomicAdd(&g_cnt[d], 1);
        if (p < PAD) g_pad[((size_t)d << PAD_LOG2) + p] = __ldg(src + e);
    }
}

// ---------------- K2: hws[i] = dinv_i * T1[x_i] ------------------------------
__global__ void k_node1(const int* __restrict__ x) {
    int i = blockIdx.x * blockDim.x + threadIdx.x;
    if (i >= N_NODES) return;
    float dv = rsqrtf((float)(__ldg(&g_cnt[i]) + 1));   // +1 self loop
    int xi = __ldg(x + i);
    const float4* tp = (const float4*)(g_t1 + (size_t)xi * HID);
    float4* o = (float4*)(g_hws + (size_t)i * HID);
#pragma unroll
    for (int q = 0; q < 4; q++) {
        float4 v = __ldg(tp + q);
        o[q] = make_float4(v.x * dv, v.y * dv, v.z * dv, v.w * dv);
    }
}

// ---------------- K3/K5: warp-per-node gather (R5-proven minimal loop) -------
__global__ void k_gather() {
    int node = (blockIdx.x * blockDim.x + threadIdx.x) >> 5;
    if (node >= N_NODES) return;
    int lane = threadIdx.x & 31;
    int q = lane & 3;                          // quarter of feature row (float4)
    int cnt = __ldg(&g_cnt[node]);
    if (cnt > PAD) cnt = PAD;
    const int* adj = g_pad + ((size_t)node << PAD_LOG2);

    float4 acc = make_float4(0.f, 0.f, 0.f, 0.f);
    for (int p = lane >> 2; p < cnt; p += 8) {
        int s = __ldg(adj + p);
        float4 v = __ldg((const float4*)(g_hws + (size_t)s * HID) + q);
        acc.x += v.x; acc.y += v.y; acc.z += v.z; acc.w += v.w;
    }
#pragma unroll
    for (int off = 4; off < 32; off <<= 1) {
        acc.x += __shfl_xor_sync(0xffffffffu, acc.x, off);
        acc.y += __shfl_xor_sync(0xffffffffu, acc.y, off);
        acc.z += __shfl_xor_sync(0xffffffffu, acc.z, off);
        acc.w += __shfl_xor_sync(0xffffffffu, acc.w, off);
    }
    if (lane < 4) {                            // lane == q
        float4 self = __ldg((const float4*)(g_hws + (size_t)node * HID) + lane);
        acc.x += self.x; acc.y += self.y; acc.z += self.z; acc.w += self.w;
        ((float4*)(g_acc + (size_t)node * HID))[lane] = acc;
    }
}

// ---------------- K4: h1 = relu(dv*acc + b1); h1@W2; scale -> hws ------------
__global__ void k_node2(const float* __restrict__ W2, const float* __restrict__ b1) {
    __shared__ float sW[HID * HID];
    __shared__ float sb[HID];
    if (threadIdx.x < HID * HID) sW[threadIdx.x] = W2[threadIdx.x];
    if (threadIdx.x < HID)       sb[threadIdx.x] = b1[threadIdx.x];
    __syncthreads();
    int i = blockIdx.x * blockDim.x + threadIdx.x;
    if (i >= N_NODES) return;

    float dv = rsqrtf((float)(__ldg(&g_cnt[i]) + 1));
    float h1[HID];
    const float4* ap = (const float4*)(g_acc + (size_t)i * HID);
#pragma unroll
    for (int q = 0; q < 4; q++) {
        float4 v = ap[q];
        h1[4*q+0] = fmaxf(fmaf(dv, v.x, sb[4*q+0]), 0.0f);
        h1[4*q+1] = fmaxf(fmaf(dv, v.y, sb[4*q+1]), 0.0f);
        h1[4*q+2] = fmaxf(fmaf(dv, v.z, sb[4*q+2]), 0.0f);
        h1[4*q+3] = fmaxf(fmaf(dv, v.w, sb[4*q+3]), 0.0f);
    }
    float4* o = (float4*)(g_hws + (size_t)i * HID);
#pragma unroll
    for (int q = 0; q < 4; q++) {
        float4 r;
        float* rp = (float*)&r;
#pragma unroll
        for (int jj = 0; jj < 4; jj++) {
            int j = 4*q + jj;
            float s = 0.0f;
#pragma unroll
            for (int k = 0; k < HID; k++) s = fmaf(h1[k], sW[k*HID + j], s);
            rp[jj] = s * dv;
        }
        o[q] = r;
    }
}

// ---------------- K6: h2 = relu(dv*acc + b2); mean-pool (run-aggregated) -----
__global__ void k_pool(const int* __restrict__ batch, const float* __restrict__ b2) {
    int t = blockIdx.x * blockDim.x + threadIdx.x;
    int start = t * POOL_CHUNK;
    if (start >= N_NODES) return;
    int end = min(start + POOL_CHUNK, N_NODES);

    float sb[HID];
#pragma unroll
    for (int j = 0; j < HID; j++) sb[j] = __ldg(b2 + j);

    float lacc[HID];
#pragma unroll
    for (int j = 0; j < HID; j++) lacc[j] = 0.0f;
    float lcnt = 0.0f;
    int cur = __ldg(batch + start);

    for (int i = start; i < end; i++) {
        int bg = __ldg(batch + i);
        if (bg != cur) {
            float* gp = g_gsum + (size_t)cur * HID;
#pragma unroll
            for (int q = 0; q < 4; q++)
                red_add_v4(gp + 4*q, make_float4(lacc[4*q], lacc[4*q+1], lacc[4*q+2], lacc[4*q+3]));
            atomicAdd(&g_gcnt[cur], lcnt);
#pragma unroll
            for (int j = 0; j < HID; j++) lacc[j] = 0.0f;
            lcnt = 0.0f;
            cur = bg;
        }
        float dv = rsqrtf((float)(g_cnt[i] + 1));
        const float4* ap = (const float4*)(g_acc + (size_t)i * HID);
#pragma unroll
        for (int q = 0; q < 4; q++) {
            float4 v = ap[q];
            lacc[4*q+0] += fmaxf(fmaf(dv, v.x, sb[4*q+0]), 0.0f);
            lacc[4*q+1] += fmaxf(fmaf(dv, v.y, sb[4*q+1]), 0.0f);
            lacc[4*q+2] += fmaxf(fmaf(dv, v.z, sb[4*q+2]), 0.0f);
            lacc[4*q+3] += fmaxf(fmaf(dv, v.w, sb[4*q+3]), 0.0f);
        }
        lcnt += 1.0f;
        g_cnt[i] = 0;                          // self-clean for next replay
    }
    float* gp = g_gsum + (size_t)cur * HID;
#pragma unroll
    for (int q = 0; q < 4; q++)
        red_add_v4(gp + 4*q, make_float4(lacc[4*q], lacc[4*q+1], lacc[4*q+2], lacc[4*q+3]));
    atomicAdd(&g_gcnt[cur], lcnt);
}

// ---------------- K7: classifier head + self-clean of pool buffers -----------
__global__ void k_out(const float* __restrict__ Wc, const float* __restrict__ bc,
                      float* __restrict__ out) {
    __shared__ float sW[HID * LABELS];
    __shared__ float sb[LABELS];
    if (threadIdx.x < HID * LABELS) sW[threadIdx.x] = Wc[threadIdx.x];
    if (threadIdx.x < LABELS)       sb[threadIdx.x] = bc[threadIdx.x];
    __syncthreads();
    int g = blockIdx.x * blockDim.x + threadIdx.x;
    if (g >= N_GRAPHS) return;

    float inv = 1.0f / fmaxf(g_gcnt[g], 1.0f);
    float p[HID];
#pragma unroll
    for (int k = 0; k < HID; k++) p[k] = g_gsum[(size_t)g * HID + k] * inv;
#pragma unroll
    for (int l = 0; l < LABELS; l++) {
        float s = sb[l];
#pragma unroll
        for (int k = 0; k < HID; k++) s = fmaf(p[k], sW[k*LABELS + l], s);
        out[(size_t)g * LABELS + l] = s;
    }
    // self-clean for next replay
#pragma unroll
    for (int k = 0; k < HID; k++) g_gsum[(size_t)g * HID + k] = 0.0f;
    g_gcnt[g] = 0.0f;
}

// ---------------- launch ------------------------------------------------------
extern "C" void kernel_launch(void* const* d_in, const int* in_sizes, int n_in,
                              void* d_out, int out_size) {
    const int*   x     = (const int*)  d_in[0];
    const int*   ei    = (const int*)  d_in[1];
    const int*   batch = (const int*)  d_in[2];
    const float* emb   = (const float*)d_in[3];
    const float* W1    = (const float*)d_in[4];
    const float* b1    = (const float*)d_in[5];
    const float* W2    = (const float*)d_in[6];
    const float* b2    = (const float*)d_in[7];
    const float* Wc    = (const float*)d_in[8];
    const float* bc    = (const float*)d_in[9];
    float* out = (float*)d_out;

    const int* src = ei;             // edge_index[0]
    const int* dst = ei + N_EDGES;   // edge_index[1]

    const int TB = 256;
    int edge_t2 = (N_EDGES + 1) / 2;
    int gather_blocks = (N_NODES * 32 + TB - 1) / TB;
    int pool_threads = (N_NODES + POOL_CHUNK - 1) / POOL_CHUNK;

    k_t1    <<<1, 128>>>(emb, W1);                              // 0
    k_fill  <<<(edge_t2 + TB - 1) / TB, TB>>>(src, dst);        // 1
    k_node1 <<<(N_NODES + TB - 1) / TB, TB>>>(x);               // 2
    k_gather<<<gather_blocks, TB>>>();                          // 3
    k_node2 <<<(N_NODES + TB - 1) / TB, TB>>>(W2, b1);          // 4
    k_gather<<<gather_blocks, TB>>>();                          // 5  <- ncu
    k_pool  <<<(pool_threads + TB - 1) / TB, TB>>>(batch, b2);  // 6
    k_out   <<<(N_GRAPHS + TB - 1) / TB, TB>>>(Wc, bc, out);    // 7
}

// round 10
// speedup vs baseline: 1.3402x; 1.0172x over previous
#include <cuda_runtime.h>
#include <cuda_bf16.h>

#define N_NODES  100000
#define N_EDGES  3200000
#define N_GRAPHS 512
#define VOCAB    128
#define HID      16
#define LABELS   10
#define POOL_CHUNK 8
#define PAD_LOG2 7
#define PAD      (1 << PAD_LOG2)     // max in-degree capacity (actual max ~70)

// ---------------- scratch (device globals; zero at load, self-cleaned) -------
__device__ int   g_cnt [N_NODES];            // in-degree; zeroed by k_pool
__device__ int   g_pad [(size_t)N_NODES * PAD];  // padded adjacency (src lists)
__device__ float g_t1  [VOCAB * HID];        // T1 = emb @ W1
__device__ float g_hws [N_NODES * HID];      // scaled features (gather source)
__device__ float g_acc [N_NODES * HID];      // aggregation result
__device__ float g_gsum[N_GRAPHS * HID];     // zeroed by k_out
__device__ float g_gcnt[N_GRAPHS];           // zeroed by k_out

__device__ __forceinline__ void red_add_v4(float* addr, float4 v) {
    asm volatile("red.global.add.v4.f32 [%0], {%1,%2,%3,%4};"
                 :: "l"(addr), "f"(v.x), "f"(v.y), "f"(v.z), "f"(v.w)
                 : "memory");
}

// ---------------- K0: T1 = emb @ W1 (one block, 128 threads) -----------------
__global__ void k_t1(const float* __restrict__ emb, const float* __restrict__ W1) {
    __shared__ float sW[HID * HID];
    int t = threadIdx.x;                 // 0..127 = vocab row
    sW[t] = W1[t]; sW[t + 128] = W1[t + 128];
    __syncthreads();
    float e[HID];
    const float4* ep = (const float4*)(emb + (size_t)t * HID);
#pragma unroll
    for (int q = 0; q < 4; q++) {
        float4 v = __ldg(ep + q);
        e[4*q+0] = v.x; e[4*q+1] = v.y; e[4*q+2] = v.z; e[4*q+3] = v.w;
    }
#pragma unroll
    for (int j = 0; j < HID; j++) {
        float s = 0.0f;
#pragma unroll
        for (int k = 0; k < HID; k++) s = fmaf(e[k], sW[k*HID + j], s);
        g_t1[t * HID + j] = s;
    }
}

// ---------------- K1: single-pass padded-adjacency build (1 edge/thread) -----
__global__ void k_fill(const int* __restrict__ src, const int* __restrict__ dst) {
    int e = blockIdx.x * blockDim.x + threadIdx.x;
    if (e >= N_EDGES) return;
    int s = __ldg(src + e);
    int d = __ldg(dst + e);
    int p = atomicAdd(&g_cnt[d], 1);
    if (p < PAD) g_pad[((size_t)d << PAD_LOG2) + p] = s;
}

// ---------------- K2: hws[i] = dinv_i * T1[x_i] ------------------------------
__global__ void k_node1(const int* __restrict__ x) {
    int i = blockIdx.x * blockDim.x + threadIdx.x;
    if (i >= N_NODES) return;
    float dv = rsqrtf((float)(__ldg(&g_cnt[i]) + 1));   // +1 self loop
    int xi = __ldg(x + i);
    const float4* tp = (const float4*)(g_t1 + (size_t)xi * HID);
    float4* o = (float4*)(g_hws + (size_t)i * HID);
#pragma unroll
    for (int q = 0; q < 4; q++) {
        float4 v = __ldg(tp + q);
        o[q] = make_float4(v.x * dv, v.y * dv, v.z * dv, v.w * dv);
    }
}

// ---------------- K3/K5: warp-per-node gather, index-prefetch pipelined ------
__global__ void k_gather() {
    int node = (blockIdx.x * blockDim.x + threadIdx.x) >> 5;
    if (node >= N_NODES) return;
    int lane = threadIdx.x & 31;
    int q = lane & 3;                          // quarter of feature row (float4)
    int cnt = __ldg(&g_cnt[node]);
    if (cnt > PAD) cnt = PAD;
    const int* adj = g_pad + ((size_t)node << PAD_LOG2);

    float4 acc = make_float4(0.f, 0.f, 0.f, 0.f);
    int p = lane >> 2;
    int s_cur = (p < cnt) ? __ldg(adj + p) : 0;
    while (p < cnt) {
        int pn = p + 8;
        int s_nxt = (pn < cnt) ? __ldg(adj + pn) : 0;   // prefetch next index
        float4 v = __ldg((const float4*)(g_hws + (size_t)s_cur * HID) + q);
        acc.x += v.x; acc.y += v.y; acc.z += v.z; acc.w += v.w;
        p = pn; s_cur = s_nxt;
    }
#pragma unroll
    for (int off = 4; off < 32; off <<= 1) {
        acc.x += __shfl_xor_sync(0xffffffffu, acc.x, off);
        acc.y += __shfl_xor_sync(0xffffffffu, acc.y, off);
        acc.z += __shfl_xor_sync(0xffffffffu, acc.z, off);
        acc.w += __shfl_xor_sync(0xffffffffu, acc.w, off);
    }
    if (lane < 4) {                            // lane == q
        float4 self = __ldg((const float4*)(g_hws + (size_t)node * HID) + lane);
        acc.x += self.x; acc.y += self.y; acc.z += self.z; acc.w += self.w;
        ((float4*)(g_acc + (size_t)node * HID))[lane] = acc;
    }
}

// ---------------- K4: h1 = relu(dv*acc + b1); h1@W2; scale -> hws ------------
// 4 threads per node: thread handles quarter q of node i. Row loads are shared
// across the 4 threads via L1; occupancy 4x vs 1-thread-per-node.
__global__ void k_node2(const float* __restrict__ W2, const float* __restrict__ b1) {
    __shared__ float sW[HID * HID];
    __shared__ float sb[HID];
    if (threadIdx.x < HID * HID) sW[threadIdx.x] = W2[threadIdx.x];
    if (threadIdx.x < HID)       sb[threadIdx.x] = b1[threadIdx.x];
    __syncthreads();
    int t = blockIdx.x * blockDim.x + threadIdx.x;
    int i = t >> 2;
    if (i >= N_NODES) return;
    int q = t & 3;

    float dv = rsqrtf((float)(__ldg(&g_cnt[i]) + 1));
    float h1[HID];
    const float4* ap = (const float4*)(g_acc + (size_t)i * HID);
#pragma unroll
    for (int qq = 0; qq < 4; qq++) {
        float4 v = __ldg(ap + qq);
        h1[4*qq+0] = fmaxf(fmaf(dv, v.x, sb[4*qq+0]), 0.0f);
        h1[4*qq+1] = fmaxf(fmaf(dv, v.y, sb[4*qq+1]), 0.0f);
        h1[4*qq+2] = fmaxf(fmaf(dv, v.z, sb[4*qq+2]), 0.0f);
        h1[4*qq+3] = fmaxf(fmaf(dv, v.w, sb[4*qq+3]), 0.0f);
    }
    float4 r;
    float* rp = (float*)&r;
#pragma unroll
    for (int jj = 0; jj < 4; jj++) {
        int j = 4*q + jj;
        float s = 0.0f;
#pragma unroll
        for (int k = 0; k < HID; k++) s = fmaf(h1[k], sW[k*HID + j], s);
        rp[jj] = s * dv;
    }
    ((float4*)(g_hws + (size_t)i * HID))[q] = r;
}

// ---------------- K6: h2 = relu(dv*acc + b2); mean-pool (run-aggregated) -----
__global__ void k_pool(const int* __restrict__ batch, const float* __restrict__ b2) {
    int t = blockIdx.x * blockDim.x + threadIdx.x;
    int start = t * POOL_CHUNK;
    if (start >= N_NODES) return;
    int end = min(start + POOL_CHUNK, N_NODES);

    float sb[HID];
#pragma unroll
    for (int j = 0; j < HID; j++) sb[j] = __ldg(b2 + j);

    float lacc[HID];
#pragma unroll
    for (int j = 0; j < HID; j++) lacc[j] = 0.0f;
    float lcnt = 0.0f;
    int cur = __ldg(batch + start);

    for (int i = start; i < end; i++) {
        int bg = __ldg(batch + i);
        if (bg != cur) {
            float* gp = g_gsum + (size_t)cur * HID;
#pragma unroll
            for (int q = 0; q < 4; q++)
                red_add_v4(gp + 4*q, make_float4(lacc[4*q], lacc[4*q+1], lacc[4*q+2], lacc[4*q+3]));
            atomicAdd(&g_gcnt[cur], lcnt);
#pragma unroll
            for (int j = 0; j < HID; j++) lacc[j] = 0.0f;
            lcnt = 0.0f;
            cur = bg;
        }
        float dv = rsqrtf((float)(g_cnt[i] + 1));
        const float4* ap = (const float4*)(g_acc + (size_t)i * HID);
#pragma unroll
        for (int q = 0; q < 4; q++) {
            float4 v = ap[q];
            lacc[4*q+0] += fmaxf(fmaf(dv, v.x, sb[4*q+0]), 0.0f);
            lacc[4*q+1] += fmaxf(fmaf(dv, v.y, sb[4*q+1]), 0.0f);
            lacc[4*q+2] += fmaxf(fmaf(dv, v.z, sb[4*q+2]), 0.0f);
            lacc[4*q+3] += fmaxf(fmaf(dv, v.w, sb[4*q+3]), 0.0f);
        }
        lcnt += 1.0f;
        g_cnt[i] = 0;                          // self-clean for next replay
    }
    float* gp = g_gsum + (size_t)cur * HID;
#pragma unroll
    for (int q = 0; q < 4; q++)
        red_add_v4(gp + 4*q, make_float4(lacc[4*q], lacc[4*q+1], lacc[4*q+2], lacc[4*q+3]));
    atomicAdd(&g_gcnt[cur], lcnt);
}

// ---------------- K7: classifier head + self-clean of pool buffers -----------
__global__ void k_out(const float* __restrict__ Wc, const float* __restrict__ bc,
                      float* __restrict__ out) {
    __shared__ float sW[HID * LABELS];
    __shared__ float sb[LABELS];
    if (threadIdx.x < HID * LABELS) sW[threadIdx.x] = Wc[threadIdx.x];
    if (threadIdx.x < LABELS)       sb[threadIdx.x] = bc[threadIdx.x];
    __syncthreads();
    int g = blockIdx.x * blockDim.x + threadIdx.x;
    if (g >= N_GRAPHS) return;

    float inv = 1.0f / fmaxf(g_gcnt[g], 1.0f);
    float p[HID];
#pragma unroll
    for (int k = 0; k < HID; k++) p[k] = g_gsum[(size_t)g * HID + k] * inv;
#pragma unroll
    for (int l = 0; l < LABELS; l++) {
        float s = sb[l];
#pragma unroll
        for (int k = 0; k < HID; k++) s = fmaf(p[k], sW[k*LABELS + l], s);
        out[(size_t)g * LABELS + l] = s;
    }
    // self-clean for next replay
#pragma unroll
    for (int k = 0; k < HID; k++) g_gsum[(size_t)g * HID + k] = 0.0f;
    g_gcnt[g] = 0.0f;
}

// ---------------- launch ------------------------------------------------------
extern "C" void kernel_launch(void* const* d_in, const int* in_sizes, int n_in,
                              void* d_out, int out_size) {
    const int*   x     = (const int*)  d_in[0];
    const int*   ei    = (const int*)  d_in[1];
    const int*   batch = (const int*)  d_in[2];
    const float* emb   = (const float*)d_in[3];
    const float* W1    = (const float*)d_in[4];
    const float* b1    = (const float*)d_in[5];
    const float* W2    = (const float*)d_in[6];
    const float* b2    = (const float*)d_in[7];
    const float* Wc    = (const float*)d_in[8];
    const float* bc    = (const float*)d_in[9];
    float* out = (float*)d_out;

    const int* src = ei;             // edge_index[0]
    const int* dst = ei + N_EDGES;   // edge_index[1]

    const int TB = 256;
    int gather_blocks = (N_NODES * 32 + TB - 1) / TB;
    int pool_threads = (N_NODES + POOL_CHUNK - 1) / POOL_CHUNK;

    k_t1    <<<1, 128>>>(emb, W1);                              // 0
    k_fill  <<<(N_EDGES + TB - 1) / TB, TB>>>(src, dst);        // 1
    k_node1 <<<(N_NODES + TB - 1) / TB, TB>>>(x);               // 2
    k_gather<<<gather_blocks, TB>>>();                          // 3
    k_node2 <<<(N_NODES * 4 + TB - 1) / TB, TB>>>(W2, b1);      // 4
    k_gather<<<gather_blocks, TB>>>();                          // 5  <- ncu
    k_pool  <<<(pool_threads + TB - 1) / TB, TB>>>(batch, b2);  // 6
    k_out   <<<(N_GRAPHS + TB - 1) / TB, TB>>>(Wc, bc, out);    // 7
}